// round 6
// baseline (speedup 1.0000x reference)
#include <cuda_runtime.h>
#include <cstdint>
#include <cstddef>

#define NIMG 32
#define CIN  128
#define HH   64
#define WW   64
#define COUTC 256

// int8 scratch (allocation-free: __device__ globals)
__device__ __align__(16) unsigned char g_x8[(size_t)NIMG * HH * WW * CIN]; // [n][h][w][cin], 0/1
__device__ __align__(16) unsigned char g_w8[9 * COUTC * CIN];              // [tap][cout][cin], -1/0/1

// ---------------- Phase A: x fp32 NCHW -> s8 NHWC ----------------
__global__ __launch_bounds__(128) void conv_x_kernel(const float* __restrict__ x) {
    int p = blockIdx.x * 128 + threadIdx.x;        // (n,h,w) flat
    int w = p & 63, h = (p >> 6) & 63, n = p >> 12;
    const float* xp = x + (size_t)n * CIN * HH * WW + h * WW + w;
    unsigned char* op = g_x8 + (size_t)p * CIN;
#pragma unroll
    for (int c16 = 0; c16 < 8; c16++) {
        uint32_t u[4];
#pragma unroll
        for (int q = 0; q < 4; q++) {
            uint32_t pk = 0;
#pragma unroll
            for (int j = 0; j < 4; j++) {
                float v = xp[(size_t)(c16 * 16 + q * 4 + j) * (HH * WW)];
                pk |= (v != 0.0f ? 1u : 0u) << (8 * j);
            }
            u[q] = pk;
        }
        *(uint4*)(op + c16 * 16) = make_uint4(u[0], u[1], u[2], u[3]);
    }
}

// ---------------- Phase B: weight fp32 OIHW -> s8 [tap][cout][cin] ----------------
__global__ __launch_bounds__(256) void conv_w_kernel(const float* __restrict__ wgt) {
    int i = blockIdx.x * 256 + threadIdx.x;
    if (i >= COUTC * CIN * 9) return;
    int kw = i % 3, kh = (i / 3) % 3, ci = (i / 9) % CIN, co = i / (9 * CIN);
    float v = wgt[i];
    signed char b = (v > 0.5f) ? 1 : (v < -0.5f ? -1 : 0);
    ((signed char*)g_w8)[((size_t)(kh * 3 + kw) * COUTC + co) * CIN + ci] = b;
}

// ---------------- Phase C: implicit GEMM via mma.sync s8 ----------------
// CTA tile: M=128 couts (one half), N=128 pixels (2 output rows), K=9*128.
// SMEM: A = 9 taps x [128 rows x 144B stride] (row = cout, 128B of cin + 16B pad)
//       B = 4 rows x 66 cols halo tile: [264 rows x 144B stride] (row = pixel, 128B cin)
#define A_STRIDE 144
#define A_TAP    (128 * A_STRIDE)          // 18432
#define SMEM_A   0
#define SMEM_B   (9 * A_TAP)               // 165888
#define SMEM_TOT (SMEM_B + 264 * A_STRIDE) // 203904

__device__ __forceinline__ uint32_t smem_u32(const void* p) {
    uint32_t a;
    asm("{ .reg .u64 t; cvta.to.shared.u64 t, %1; cvt.u32.u64 %0, t; }" : "=r"(a) : "l"(p));
    return a;
}

#define LDSM_X4(r, addr)                                                               \
    asm volatile("ldmatrix.sync.aligned.m8n8.x4.shared.b16 {%0,%1,%2,%3}, [%4];"       \
                 : "=r"((r)[0]), "=r"((r)[1]), "=r"((r)[2]), "=r"((r)[3])              \
                 : "r"(addr))

#define MMA_S8(d, a, b0, b1)                                                           \
    asm volatile("mma.sync.aligned.m16n8k32.row.col.s32.s8.s8.s32 "                    \
                 "{%0,%1,%2,%3}, {%4,%5,%6,%7}, {%8,%9}, {%0,%1,%2,%3};"               \
                 : "+r"((d)[0]), "+r"((d)[1]), "+r"((d)[2]), "+r"((d)[3])              \
                 : "r"((a)[0]), "r"((a)[1]), "r"((a)[2]), "r"((a)[3]),                 \
                   "r"(b0), "r"(b1))

__global__ __launch_bounds__(256, 1) void conv_mma_kernel(
    const float* __restrict__ bias, const float* __restrict__ sgn, float* __restrict__ out)
{
    extern __shared__ char smem[];
    uint32_t smem_base = smem_u32(smem);
    int tid = threadIdx.x, wid = tid >> 5, lane = tid & 31;
    int warp_m = wid & 3;      // 4 warps in M: 32 couts each
    int warp_n = wid >> 2;     // 2 warps in N: 64 pixels each = one output row
    int b = blockIdx.x;
    int ch = b & 1;            // cout half
    int h2 = (b >> 1) & 31;    // output row pair
    int n  = b >> 6;
    int h0 = h2 * 2;

    // ---- fill A: 9 taps x 128 couts x 128B (dest stride 144) ----
    for (int it = tid; it < 9 * 128 * 8; it += 256) {
        int c16 = it & 7, row = (it >> 3) & 127, tap = it >> 10;
        uint4 v = *(const uint4*)(g_w8 + ((size_t)(tap * COUTC + ch * 128 + row) * CIN) + c16 * 16);
        *(uint4*)(smem + SMEM_A + tap * A_TAP + row * A_STRIDE + c16 * 16) = v;
    }
    // ---- fill B: haloed input tile, 4 rows x 66 cols (zero pad) ----
    {
        const unsigned char* xn = g_x8 + (size_t)n * HH * WW * CIN;
        for (int it = tid; it < 264 * 8; it += 256) {
            int c16 = it & 7, row = it >> 3;           // 0..263
            int r = row / 66, c = row - r * 66;
            int h_in = h0 - 1 + r;
            int w_in = c - 1;
            uint4 v = make_uint4(0, 0, 0, 0);
            if ((unsigned)h_in < 64u && (unsigned)w_in < 64u)
                v = *(const uint4*)(xn + ((size_t)(h_in * 64 + w_in) * CIN) + c16 * 16);
            *(uint4*)(smem + SMEM_B + row * A_STRIDE + c16 * 16) = v;
        }
    }
    __syncthreads();

    // ldmatrix lane addressing for A (16x32 s8 row-major as 4 x m8n8.b16):
    //   MMA wants: a0 = rows 0-7 / k-bytes 0-15, a1 = rows 8-15 / k 0-15,
    //              a2 = rows 0-7 / k 16-31,      a3 = rows 8-15 / k 16-31.
    //   ldmatrix octets: lanes 0-7 -> m0, 8-15 -> m1, 16-23 -> m2, 24-31 -> m3.
    //   => octet1 (lanes 8-15) = rows 8-15 off 0; octet2 (16-23) = rows 0-7 off 16.
    uint32_t a_row   = (uint32_t)(warp_m * 32 + (lane & 7) + ((lane >> 3) & 1) * 8);
    uint32_t a_off16 = ((lane >> 4) & 1) * 16u;
    uint32_t a_lane = smem_base + SMEM_A + a_row * A_STRIDE + a_off16;
    // B x4 loads 2 n-tiles (8 pixels each):
    //   octet0 -> ntile j pixels, k-off 0 (=b0); octet1 -> same pixels, k-off16 (=b1);
    //   octet2/3 -> ntile j+1.
    uint32_t b_rowlane = (uint32_t)((lane & 7) + ((lane >> 4) & 1) * 8);
    uint32_t b_off16   = ((lane >> 3) & 1) * 16u;

    int acc[2][8][4];
#pragma unroll
    for (int i = 0; i < 2; i++)
#pragma unroll
        for (int j = 0; j < 8; j++)
#pragma unroll
            for (int q = 0; q < 4; q++) acc[i][j][q] = 0;

    for (int tap = 0; tap < 9; tap++) {
        int kh = tap / 3, kw = tap - kh * 3;
        uint32_t abase = a_lane + (uint32_t)tap * A_TAP;
        uint32_t bbase = smem_base + SMEM_B
                       + (uint32_t)(((warp_n + kh) * 66 + kw + b_rowlane)) * A_STRIDE + b_off16;
#pragma unroll
        for (int kc = 0; kc < 4; kc++) {
            uint32_t af[2][4];
            LDSM_X4(af[0], abase + kc * 32);
            LDSM_X4(af[1], abase + 16 * A_STRIDE + kc * 32);
            uint32_t bf[4][4];
#pragma unroll
            for (int jp = 0; jp < 4; jp++)
                LDSM_X4(bf[jp], bbase + (uint32_t)(jp * 16) * A_STRIDE + kc * 32);
#pragma unroll
            for (int i = 0; i < 2; i++)
#pragma unroll
                for (int j = 0; j < 8; j++)
                    MMA_S8(acc[i][j], af[i], bf[j >> 1][(j & 1) * 2], bf[j >> 1][(j & 1) * 2 + 1]);
        }
    }

    // ---- epilogue: (acc + bias) * sign >= 0 ? 1 : 0 ----
    int gq = lane >> 2, tig = lane & 3;
    int hrow = h0 + warp_n;
#pragma unroll
    for (int i = 0; i < 2; i++) {
#pragma unroll
        for (int half = 0; half < 2; half++) {
            int cout = ch * 128 + warp_m * 32 + i * 16 + gq + half * 8;
            float bv = bias[cout];
            float sv = sgn[cout];
            float* op = out + (((size_t)n * COUTC + cout) * HH + hrow) * WW;
#pragma unroll
            for (int j = 0; j < 8; j++) {
                int w = j * 8 + 2 * tig;
                float f0 = (float)acc[i][j][half * 2 + 0] + bv;
                float f1 = (float)acc[i][j][half * 2 + 1] + bv;
                float2 r;
                r.x = (f0 * sv >= 0.0f) ? 1.0f : 0.0f;
                r.y = (f1 * sv >= 0.0f) ? 1.0f : 0.0f;
                *(float2*)(op + w) = r;
            }
        }
    }
}

// ---------------- launch ----------------
extern "C" void kernel_launch(void* const* d_in, const int* in_sizes, int n_in,
                              void* d_out, int out_size) {
    const float* x    = (const float*)d_in[0];
    const float* wgt  = (const float*)d_in[1];
    const float* bias = (const float*)d_in[2];
    const float* sgn  = (const float*)d_in[3];
    float* out = (float*)d_out;

    cudaFuncSetAttribute(conv_mma_kernel, cudaFuncAttributeMaxDynamicSharedMemorySize, SMEM_TOT);

    conv_x_kernel<<<(NIMG * HH * WW) / 128, 128>>>(x);
    conv_w_kernel<<<(COUTC * CIN * 9 + 255) / 256, 256>>>(wgt);
    conv_mma_kernel<<<NIMG * 32 * 2, 256, SMEM_TOT>>>(bias, sgn, out);
}

// round 7
// speedup vs baseline: 1.0896x; 1.0896x over previous
#include <cuda_runtime.h>
#include <cstdint>
#include <cstddef>

#define NIMG 32
#define CIN  128
#define HH   64
#define WW   64
#define COUTC 256

// int8 scratch (allocation-free: __device__ globals)
__device__ __align__(16) unsigned char g_x8[(size_t)NIMG * HH * WW * CIN]; // [n][h][w][cin], 0/1
__device__ __align__(16) unsigned char g_w8[9 * COUTC * CIN];              // [tap][cout][cin], -1/0/1

// ---------------- Phase A: x fp32 NCHW -> s8 NHWC ----------------
__global__ __launch_bounds__(128) void conv_x_kernel(const float* __restrict__ x) {
    int p = blockIdx.x * 128 + threadIdx.x;        // (n,h,w) flat
    int w = p & 63, h = (p >> 6) & 63, n = p >> 12;
    const float* xp = x + (size_t)n * CIN * HH * WW + h * WW + w;
    unsigned char* op = g_x8 + (size_t)p * CIN;
#pragma unroll
    for (int c16 = 0; c16 < 8; c16++) {
        uint32_t u[4];
#pragma unroll
        for (int q = 0; q < 4; q++) {
            uint32_t pk = 0;
#pragma unroll
            for (int j = 0; j < 4; j++) {
                float v = xp[(size_t)(c16 * 16 + q * 4 + j) * (HH * WW)];
                pk |= (v != 0.0f ? 1u : 0u) << (8 * j);
            }
            u[q] = pk;
        }
        *(uint4*)(op + c16 * 16) = make_uint4(u[0], u[1], u[2], u[3]);
    }
}

// ---------------- Phase B: weight fp32 OIHW -> s8 [tap][cout][cin] ----------------
__global__ __launch_bounds__(256) void conv_w_kernel(const float* __restrict__ wgt) {
    int i = blockIdx.x * 256 + threadIdx.x;
    if (i >= COUTC * CIN * 9) return;
    int kw = i % 3, kh = (i / 3) % 3, ci = (i / 9) % CIN, co = i / (9 * CIN);
    float v = wgt[i];
    signed char b = (v > 0.5f) ? 1 : (v < -0.5f ? -1 : 0);
    ((signed char*)g_w8)[((size_t)(kh * 3 + kw) * COUTC + co) * CIN + ci] = b;
}

// ---------------- Phase C: implicit GEMM via mma.sync s8 ----------------
// CTA tile: M=128 couts (one half) x N=256 pixels (4 output rows), K=9*128 streamed per tap.
// SMEM: A = double buffer, per tap [128 rows x 144B] (row = cout, 128B cin + 16B pad)
//       B = 6 rows x 66 cols halo tile: [396 rows x 144B] (row = pixel, 128B cin)
// A prefetched per-tap via cp.async, overlapped with MMA compute of current tap.
#define A_STRIDE 144
#define A_TAP    (128 * A_STRIDE)            // 18432
#define SMEM_A   0
#define SMEM_B   (2 * A_TAP)                 // 36864
#define SMEM_TOT (SMEM_B + 396 * A_STRIDE)   // 93888

__device__ __forceinline__ uint32_t smem_u32(const void* p) {
    uint32_t a;
    asm("{ .reg .u64 t; cvta.to.shared.u64 t, %1; cvt.u32.u64 %0, t; }" : "=r"(a) : "l"(p));
    return a;
}

__device__ __forceinline__ void cp16(uint32_t dst, const void* src, int sz) {
    asm volatile("cp.async.cg.shared.global [%0], [%1], 16, %2;" :: "r"(dst), "l"(src), "r"(sz));
}
#define CP_COMMIT() asm volatile("cp.async.commit_group;" ::: "memory")
#define CP_WAIT0()  asm volatile("cp.async.wait_group 0;" ::: "memory")

#define LDSM_X4(r, addr)                                                               \
    asm volatile("ldmatrix.sync.aligned.m8n8.x4.shared.b16 {%0,%1,%2,%3}, [%4];"       \
                 : "=r"((r)[0]), "=r"((r)[1]), "=r"((r)[2]), "=r"((r)[3])              \
                 : "r"(addr))

#define MMA_S8(d, a, b0, b1)                                                           \
    asm volatile("mma.sync.aligned.m16n8k32.row.col.s32.s8.s8.s32 "                    \
                 "{%0,%1,%2,%3}, {%4,%5,%6,%7}, {%8,%9}, {%0,%1,%2,%3};"               \
                 : "+r"((d)[0]), "+r"((d)[1]), "+r"((d)[2]), "+r"((d)[3])              \
                 : "r"((a)[0]), "r"((a)[1]), "r"((a)[2]), "r"((a)[3]),                 \
                   "r"(b0), "r"(b1))

__global__ __launch_bounds__(512, 1) void conv_mma_kernel(
    const float* __restrict__ bias, const float* __restrict__ sgn, float* __restrict__ out)
{
    extern __shared__ char smem[];
    uint32_t smem_base = smem_u32(smem);
    int tid = threadIdx.x, wid = tid >> 5, lane = tid & 31;
    int warp_m = wid & 3;      // 4 warps in M: 32 couts each
    int warp_n = wid >> 2;     // 4 warps in N: 64 pixels each = one output row
    int b = blockIdx.x;
    int ch = b & 1;            // cout half
    int h4 = (b >> 1) & 15;    // output row quad
    int n  = b >> 5;
    int h0 = h4 * 4;

    // ---- async fill B: haloed input tile, 6 rows x 66 cols (zero fill halo) ----
    {
        const unsigned char* xn = g_x8 + (size_t)n * HH * WW * CIN;
        for (int it = tid; it < 396 * 8; it += 512) {
            int c16 = it & 7, row = it >> 3;           // 0..395
            int r = row / 66, c = row - r * 66;
            int h_in = h0 - 1 + r;
            int w_in = c - 1;
            bool ok = ((unsigned)h_in < 64u) && ((unsigned)w_in < 64u);
            const unsigned char* src = ok
                ? xn + ((size_t)(h_in * 64 + w_in) * CIN) + c16 * 16 : xn;
            cp16(smem_base + SMEM_B + row * A_STRIDE + c16 * 16, src, ok ? 16 : 0);
        }
    }
    // ---- async fill A tap 0 -> buf 0 ----
    for (int it = tid; it < 1024; it += 512) {
        int c16 = it & 7, row = it >> 3;
        cp16(smem_base + SMEM_A + row * A_STRIDE + c16 * 16,
             g_w8 + ((size_t)(0 * COUTC + ch * 128 + row) * CIN) + c16 * 16, 16);
    }
    CP_COMMIT();
    CP_WAIT0();
    __syncthreads();

    // ldmatrix lane addressing for A (16x32 s8 row-major as 4 x m8n8.b16):
    //   a0 = rows 0-7 / k 0-15, a1 = rows 8-15 / k 0-15, a2 = rows 0-7 / k 16-31, a3 = rows 8-15 / k 16-31
    uint32_t a_row   = (uint32_t)(warp_m * 32 + (lane & 7) + ((lane >> 3) & 1) * 8);
    uint32_t a_off16 = ((lane >> 4) & 1) * 16u;
    uint32_t a_lane  = smem_base + SMEM_A + a_row * A_STRIDE + a_off16;
    // B x4: octet0 -> ntile j k0-15 (b0), octet1 -> k16-31 (b1), octets 2/3 -> ntile j+1
    uint32_t b_rowlane = (uint32_t)((lane & 7) + ((lane >> 4) & 1) * 8);
    uint32_t b_off16   = ((lane >> 3) & 1) * 16u;

    int acc[2][8][4];
#pragma unroll
    for (int i = 0; i < 2; i++)
#pragma unroll
        for (int j = 0; j < 8; j++)
#pragma unroll
            for (int q = 0; q < 4; q++) acc[i][j][q] = 0;

    for (int t = 0; t < 9; t++) {
        // prefetch next tap's A into the other buffer (overlaps with compute below)
        if (t < 8) {
            for (int it = tid; it < 1024; it += 512) {
                int c16 = it & 7, row = it >> 3;
                cp16(smem_base + SMEM_A + (uint32_t)((t + 1) & 1) * A_TAP + row * A_STRIDE + c16 * 16,
                     g_w8 + ((size_t)((t + 1) * COUTC + ch * 128 + row) * CIN) + c16 * 16, 16);
            }
            CP_COMMIT();
        }

        int kh = t / 3, kw = t - kh * 3;
        uint32_t abase = a_lane + (uint32_t)(t & 1) * A_TAP;
        uint32_t bbase = smem_base + SMEM_B
                       + (uint32_t)((warp_n + kh) * 66 + kw + b_rowlane) * A_STRIDE + b_off16;
#pragma unroll
        for (int kc = 0; kc < 4; kc++) {
            uint32_t af[2][4];
            LDSM_X4(af[0], abase + kc * 32);
            LDSM_X4(af[1], abase + 16 * A_STRIDE + kc * 32);
            uint32_t bf[4][4];
#pragma unroll
            for (int jp = 0; jp < 4; jp++)
                LDSM_X4(bf[jp], bbase + (uint32_t)(jp * 16) * A_STRIDE + kc * 32);
#pragma unroll
            for (int i = 0; i < 2; i++)
#pragma unroll
                for (int j = 0; j < 8; j++)
                    MMA_S8(acc[i][j], af[i], bf[j >> 1][(j & 1) * 2], bf[j >> 1][(j & 1) * 2 + 1]);
        }

        if (t < 8) {
            CP_WAIT0();
            __syncthreads();
        }
    }

    // ---- epilogue: (acc + bias) * sign >= 0 ? 1 : 0 ----
    int gq = lane >> 2, tig = lane & 3;
    int hrow = h0 + warp_n;
#pragma unroll
    for (int i = 0; i < 2; i++) {
#pragma unroll
        for (int half = 0; half < 2; half++) {
            int cout = ch * 128 + warp_m * 32 + i * 16 + gq + half * 8;
            float bv = bias[cout];
            float sv = sgn[cout];
            float* op = out + (((size_t)n * COUTC + cout) * HH + hrow) * WW;
#pragma unroll
            for (int j = 0; j < 8; j++) {
                int w = j * 8 + 2 * tig;
                float f0 = (float)acc[i][j][half * 2 + 0] + bv;
                float f1 = (float)acc[i][j][half * 2 + 1] + bv;
                float2 r;
                r.x = (f0 * sv >= 0.0f) ? 1.0f : 0.0f;
                r.y = (f1 * sv >= 0.0f) ? 1.0f : 0.0f;
                *(float2*)(op + w) = r;
            }
        }
    }
}

// ---------------- launch ----------------
extern "C" void kernel_launch(void* const* d_in, const int* in_sizes, int n_in,
                              void* d_out, int out_size) {
    const float* x    = (const float*)d_in[0];
    const float* wgt  = (const float*)d_in[1];
    const float* bias = (const float*)d_in[2];
    const float* sgn  = (const float*)d_in[3];
    float* out = (float*)d_out;

    cudaFuncSetAttribute(conv_mma_kernel, cudaFuncAttributeMaxDynamicSharedMemorySize, SMEM_TOT);

    conv_x_kernel<<<(NIMG * HH * WW) / 128, 128>>>(x);
    conv_w_kernel<<<(COUTC * CIN * 9 + 255) / 256, 256>>>(wgt);
    conv_mma_kernel<<<NIMG * 16 * 2, 512, SMEM_TOT>>>(bias, sgn, out);
}

// round 8
// speedup vs baseline: 1.8119x; 1.6628x over previous
#include <cuda_runtime.h>
#include <cstdint>
#include <cstddef>

#define NIMG 32
#define CIN  128
#define HH   64
#define WW   64
#define COUTC 256

// int8 scratch (allocation-free: __device__ globals)
__device__ __align__(16) unsigned char g_x8[(size_t)NIMG * HH * WW * CIN]; // [n][h][w][cin], 0/1
__device__ __align__(16) unsigned char g_w8[9 * COUTC * CIN];              // [tap][cout][cin], -1/0/1

// ---------------- Phase A: x fp32 NCHW -> s8 NHWC ----------------
__global__ __launch_bounds__(128) void conv_x_kernel(const float* __restrict__ x) {
    int p = blockIdx.x * 128 + threadIdx.x;        // (n,h,w) flat
    int w = p & 63, h = (p >> 6) & 63, n = p >> 12;
    const float* xp = x + (size_t)n * CIN * HH * WW + h * WW + w;
    unsigned char* op = g_x8 + (size_t)p * CIN;
#pragma unroll
    for (int c16 = 0; c16 < 8; c16++) {
        uint32_t u[4];
#pragma unroll
        for (int q = 0; q < 4; q++) {
            uint32_t pk = 0;
#pragma unroll
            for (int j = 0; j < 4; j++) {
                float v = xp[(size_t)(c16 * 16 + q * 4 + j) * (HH * WW)];
                pk |= (v != 0.0f ? 1u : 0u) << (8 * j);
            }
            u[q] = pk;
        }
        *(uint4*)(op + c16 * 16) = make_uint4(u[0], u[1], u[2], u[3]);
    }
}

// ---------------- Phase B: weight fp32 OIHW -> s8 [tap][cout][cin] ----------------
__global__ __launch_bounds__(256) void conv_w_kernel(const float* __restrict__ wgt) {
    int i = blockIdx.x * 256 + threadIdx.x;
    if (i >= COUTC * CIN * 9) return;
    int kw = i % 3, kh = (i / 3) % 3, ci = (i / 9) % CIN, co = i / (9 * CIN);
    float v = wgt[i];
    signed char b = (v > 0.5f) ? 1 : (v < -0.5f ? -1 : 0);
    ((signed char*)g_w8)[((size_t)(kh * 3 + kw) * COUTC + co) * CIN + ci] = b;
}

// ---------------- Phase C: hybrid implicit GEMM: mma.sync (tensor) + dp4a (fma pipe) ----------------
// CTA tile: M=128 couts (one half) x N=256 pixels (4 output rows), K=9*128.
//   warps 0-7 : mma.sync path, output rows h0+0, h0+1 (tensor unit, ~264 MAC/cyc/SM)
//   warps 8-15: dp4a path,      output rows h0+2, h0+3 (fma pipe,    ~256 MAC/cyc/SM)
// SMEM: A = 9 taps x [128 rows x 144B] (row = cout, 128B cin + 16B pad), resident
//       B = 6 rows x 66 cols halo tile: [396 rows x 144B] (row = pixel, 128B cin)
#define A_STRIDE 144
#define A_TAP    (128 * A_STRIDE)            // 18432
#define SMEM_A   0
#define SMEM_B   (9 * A_TAP)                 // 165888
#define SMEM_TOT (SMEM_B + 396 * A_STRIDE)   // 222912 (<= 227KB)

__device__ __forceinline__ uint32_t smem_u32(const void* p) {
    uint32_t a;
    asm("{ .reg .u64 t; cvta.to.shared.u64 t, %1; cvt.u32.u64 %0, t; }" : "=r"(a) : "l"(p));
    return a;
}

__device__ __forceinline__ void cp16(uint32_t dst, const void* src, int sz) {
    asm volatile("cp.async.cg.shared.global [%0], [%1], 16, %2;" :: "r"(dst), "l"(src), "r"(sz));
}
#define CP_COMMIT() asm volatile("cp.async.commit_group;" ::: "memory")
#define CP_WAIT0()  asm volatile("cp.async.wait_group 0;" ::: "memory")

#define LDSM_X4(r, addr)                                                               \
    asm volatile("ldmatrix.sync.aligned.m8n8.x4.shared.b16 {%0,%1,%2,%3}, [%4];"       \
                 : "=r"((r)[0]), "=r"((r)[1]), "=r"((r)[2]), "=r"((r)[3])              \
                 : "r"(addr))

#define MMA_S8(d, a, b0, b1)                                                           \
    asm volatile("mma.sync.aligned.m16n8k32.row.col.s32.s8.s8.s32 "                    \
                 "{%0,%1,%2,%3}, {%4,%5,%6,%7}, {%8,%9}, {%0,%1,%2,%3};"               \
                 : "+r"((d)[0]), "+r"((d)[1]), "+r"((d)[2]), "+r"((d)[3])              \
                 : "r"((a)[0]), "r"((a)[1]), "r"((a)[2]), "r"((a)[3]),                 \
                   "r"(b0), "r"(b1))

__global__ __launch_bounds__(512, 1) void conv_mma_kernel(
    const float* __restrict__ bias, const float* __restrict__ sgn, float* __restrict__ out)
{
    extern __shared__ char smem[];
    uint32_t smem_base = smem_u32(smem);
    int tid = threadIdx.x, wid = tid >> 5, lane = tid & 31;
    int b = blockIdx.x;
    int ch = b & 1;            // cout half
    int h4 = (b >> 1) & 15;    // output row quad
    int n  = b >> 5;
    int h0 = h4 * 4;

    // ---- async fill A: all 9 taps (row = cout within half) ----
    for (int it = tid; it < 9 * 128 * 8; it += 512) {
        int c16 = it & 7, row = (it >> 3) & 127, tap = it >> 10;
        cp16(smem_base + SMEM_A + tap * A_TAP + row * A_STRIDE + c16 * 16,
             g_w8 + ((size_t)(tap * COUTC + ch * 128 + row) * CIN) + c16 * 16, 16);
    }
    // ---- async fill B: haloed input tile, 6 rows x 66 cols (zero fill halo) ----
    {
        const unsigned char* xn = g_x8 + (size_t)n * HH * WW * CIN;
        for (int it = tid; it < 396 * 8; it += 512) {
            int c16 = it & 7, row = it >> 3;           // 0..395
            int r = row / 66, c = row - r * 66;
            int h_in = h0 - 1 + r;
            int w_in = c - 1;
            bool ok = ((unsigned)h_in < 64u) && ((unsigned)w_in < 64u);
            const unsigned char* src = ok
                ? xn + ((size_t)(h_in * 64 + w_in) * CIN) + c16 * 16 : xn;
            cp16(smem_base + SMEM_B + row * A_STRIDE + c16 * 16, src, ok ? 16 : 0);
        }
    }
    CP_COMMIT();
    CP_WAIT0();
    __syncthreads();

    if (wid < 8) {
        // ================= MMA path: rows h0+0, h0+1 =================
        int warp_m = wid & 3;      // 4 warps in M: 32 couts each
        int warp_n = wid >> 2;     // 2 warps in N: row h0+warp_n
        // A frag: a0 rows0-7/k0-15, a1 rows8-15/k0-15, a2 rows0-7/k16-31, a3 rows8-15/k16-31
        uint32_t a_row   = (uint32_t)(warp_m * 32 + (lane & 7) + ((lane >> 3) & 1) * 8);
        uint32_t a_off16 = ((lane >> 4) & 1) * 16u;
        uint32_t a_lane  = smem_base + SMEM_A + a_row * A_STRIDE + a_off16;
        uint32_t b_rowlane = (uint32_t)((lane & 7) + ((lane >> 4) & 1) * 8);
        uint32_t b_off16   = ((lane >> 3) & 1) * 16u;

        int acc[2][8][4];
#pragma unroll
        for (int i = 0; i < 2; i++)
#pragma unroll
            for (int j = 0; j < 8; j++)
#pragma unroll
                for (int q = 0; q < 4; q++) acc[i][j][q] = 0;

        for (int t = 0; t < 9; t++) {
            int kh = t / 3, kw = t - kh * 3;
            uint32_t abase = a_lane + (uint32_t)t * A_TAP;
            uint32_t bbase = smem_base + SMEM_B
                           + (uint32_t)((warp_n + kh) * 66 + kw + b_rowlane) * A_STRIDE + b_off16;
#pragma unroll
            for (int kc = 0; kc < 4; kc++) {
                uint32_t af[2][4];
                LDSM_X4(af[0], abase + kc * 32);
                LDSM_X4(af[1], abase + 16 * A_STRIDE + kc * 32);
                uint32_t bf[4][4];
#pragma unroll
                for (int jp = 0; jp < 4; jp++)
                    LDSM_X4(bf[jp], bbase + (uint32_t)(jp * 16) * A_STRIDE + kc * 32);
#pragma unroll
                for (int i = 0; i < 2; i++)
#pragma unroll
                    for (int j = 0; j < 8; j++)
                        MMA_S8(acc[i][j], af[i], bf[j >> 1][(j & 1) * 2], bf[j >> 1][(j & 1) * 2 + 1]);
            }
        }

        // epilogue
        int gq = lane >> 2, tig = lane & 3;
        int hrow = h0 + warp_n;
#pragma unroll
        for (int i = 0; i < 2; i++) {
#pragma unroll
            for (int half = 0; half < 2; half++) {
                int cout = ch * 128 + warp_m * 32 + i * 16 + gq + half * 8;
                float bv = bias[cout];
                float sv = sgn[cout];
                float* op = out + (((size_t)n * COUTC + cout) * HH + hrow) * WW;
#pragma unroll
                for (int j = 0; j < 8; j++) {
                    int w = j * 8 + 2 * tig;
                    float f0 = (float)acc[i][j][half * 2 + 0] + bv;
                    float f1 = (float)acc[i][j][half * 2 + 1] + bv;
                    float2 r;
                    r.x = (f0 * sv >= 0.0f) ? 1.0f : 0.0f;
                    r.y = (f1 * sv >= 0.0f) ? 1.0f : 0.0f;
                    *(float2*)(op + w) = r;
                }
            }
        }
    } else {
        // ================= dp4a path: rows h0+2, h0+3 =================
        int widx = wid - 8;
        int cb   = (widx & 3) * 32;        // cout block within half
        int cg   = lane & 3;               // cout lane (stride-4 within block)
        int pxg  = lane >> 2;              // pixel lane 0..7
        int tb2  = (widx >> 2) * 2;        // first px-tile index (0 or 2)

#pragma unroll 1
        for (int pt = 0; pt < 2; pt++) {
            int tile = tb2 + pt;            // 0..3
            int row  = 2 + (tile >> 1);     // output row offset within quad: 2 or 3
            int colb = (tile & 1) * 32;     // column base

            int acc[8][4];
#pragma unroll
            for (int i = 0; i < 8; i++)
#pragma unroll
                for (int j = 0; j < 4; j++) acc[i][j] = 0;

#pragma unroll 1
            for (int t = 0; t < 9; t++) {
                int kh = t / 3, kw = t - kh * 3;
                const char* wb = smem + SMEM_A + t * A_TAP + (cb + cg) * A_STRIDE;
                const char* xb = smem + SMEM_B
                               + ((row + kh) * 66 + kw + colb + pxg) * A_STRIDE;
#pragma unroll
                for (int k16 = 0; k16 < 8; k16++) {
                    int4 xv[4];
#pragma unroll
                    for (int j = 0; j < 4; j++)
                        xv[j] = *(const int4*)(xb + j * 8 * A_STRIDE + k16 * 16);
                    int4 wv[8];
#pragma unroll
                    for (int i = 0; i < 8; i++)
                        wv[i] = *(const int4*)(wb + i * 4 * A_STRIDE + k16 * 16);
#pragma unroll
                    for (int i = 0; i < 8; i++)
#pragma unroll
                        for (int j = 0; j < 4; j++) {
                            acc[i][j] = __dp4a(xv[j].x, wv[i].x, acc[i][j]);
                            acc[i][j] = __dp4a(xv[j].y, wv[i].y, acc[i][j]);
                            acc[i][j] = __dp4a(xv[j].z, wv[i].z, acc[i][j]);
                            acc[i][j] = __dp4a(xv[j].w, wv[i].w, acc[i][j]);
                        }
                }
            }

            // epilogue
            int hrow = h0 + row;
#pragma unroll
            for (int i = 0; i < 8; i++) {
                int cout = ch * 128 + cb + cg + i * 4;
                float bv = bias[cout];
                float sv = sgn[cout];
                float* op = out + (((size_t)n * COUTC + cout) * HH + hrow) * WW + colb + pxg;
#pragma unroll
                for (int j = 0; j < 4; j++) {
                    float f = (float)acc[i][j] + bv;
                    op[j * 8] = (f * sv >= 0.0f) ? 1.0f : 0.0f;
                }
            }
        }
    }
}

// ---------------- launch ----------------
extern "C" void kernel_launch(void* const* d_in, const int* in_sizes, int n_in,
                              void* d_out, int out_size) {
    const float* x    = (const float*)d_in[0];
    const float* wgt  = (const float*)d_in[1];
    const float* bias = (const float*)d_in[2];
    const float* sgn  = (const float*)d_in[3];
    float* out = (float*)d_out;

    cudaFuncSetAttribute(conv_mma_kernel, cudaFuncAttributeMaxDynamicSharedMemorySize, SMEM_TOT);

    conv_x_kernel<<<(NIMG * HH * WW) / 128, 128>>>(x);
    conv_w_kernel<<<(COUTC * CIN * 9 + 255) / 256, 256>>>(wgt);
    conv_mma_kernel<<<NIMG * 16 * 2, 512, SMEM_TOT>>>(bias, sgn, out);
}